// round 16
// baseline (speedup 1.0000x reference)
#include <cuda_runtime.h>
#include <cuda_bf16.h>
#include <cuda_fp16.h>
#include <math.h>
#include <stdint.h>

// Problem constants
#define B_ 2
#define T_ 2048
#define C_ 1024
#define H_ 16
#define D_ 64
#define WIN_ 512
#define K_ 1024

// GEMM tiling: CTA 128(M)x64(N), 256 threads, warp 32x32, BK=32/stage, 4 stages
#define SP 24                         // padded row stride per K16 tile (fp16) = 48 B
#define TA16 (128 * SP * 2)           // 6144 B per 128x16 A tile
#define TB16 (64 * SP * 2)            // 3072 B per 64x16 B tile
#define STAGE_B (2 * (TA16 + TB16))   // 18432 B (2 K16 sub-slabs)
#define NSTAGE 4                      // power of 2 (ring mask)
#define GSMEM (NSTAGE * STAGE_B)      // 73728 B; 3 CTAs/SM = 216 KB

// Attention smem: Qf[128*ASP] + 2 KV buffers of (K 64*ASP + V 64*ASP)
#define ASP 72
#define KV_BUF_H (128 * ASP)                 // halves per KV buffer (K+V)
#define ATTN_SMEM ((128 * ASP + 2 * KV_BUF_H) * 2)   // 55296 B

// ---------------- scratch (allocation-free) ----------------
__device__ __half g_Qf[B_*H_*T_*D_];
__device__ __half g_Kf[B_*H_*T_*D_];
__device__ __half g_Vf[B_*H_*T_*D_];
__device__ __half g_xf[B_*T_*C_];
__device__ __half g_wqf[3*C_*C_];
__device__ __half g_wpf[C_*C_];
__device__ __half g_yf[B_*T_*C_];

__device__ __forceinline__ uint32_t smem_u32(const void* p) {
    uint32_t a;
    asm("{ .reg .u64 t; cvta.to.shared.u64 t, %1; cvt.u32.u64 %0, t; }"
        : "=r"(a) : "l"(p));
    return a;
}
#define LDMX4(r0, r1, r2, r3, addr)                                          \
    asm volatile("ldmatrix.sync.aligned.m8n8.x4.shared.b16 {%0,%1,%2,%3}, [%4];" \
        : "=r"(r0), "=r"(r1), "=r"(r2), "=r"(r3) : "r"(addr))
#define LDMX4T(r0, r1, r2, r3, addr)                                         \
    asm volatile("ldmatrix.sync.aligned.m8n8.x4.trans.shared.b16 {%0,%1,%2,%3}, [%4];" \
        : "=r"(r0), "=r"(r1), "=r"(r2), "=r"(r3) : "r"(addr))
// fp16 HMMA
#define MMAH16816(c, a0, a1, a2, a3, b0, b1)                                 \
    asm volatile("mma.sync.aligned.m16n8k16.row.col.f32.f16.f16.f32 "        \
        "{%0,%1,%2,%3}, {%4,%5,%6,%7}, {%8,%9}, {%0,%1,%2,%3};"              \
        : "+f"((c)[0]), "+f"((c)[1]), "+f"((c)[2]), "+f"((c)[3])             \
        : "r"(a0), "r"(a1), "r"(a2), "r"(a3), "r"(b0), "r"(b1))
#define CP16(dst, src)                                                       \
    asm volatile("cp.async.cg.shared.global [%0], [%1], 16;" :: "r"(dst), "l"(src))
#define CP_COMMIT() asm volatile("cp.async.commit_group;" ::: "memory")
#define CP_WAIT(n)  asm volatile("cp.async.wait_group %0;" :: "n"(n) : "memory")

__device__ __forceinline__ uint32_t packh2(float a, float b) {
    __half2 h = __floats2half2_rn(a, b);
    return *(uint32_t*)&h;
}

// ---------------- fused fp32->fp16 convert for x, Wqkv, Wproj -------------
#define N4_X  (B_*T_*C_/4)
#define N4_WQ (3*C_*C_/4)
#define N4_WP (C_*C_/4)
__global__ __launch_bounds__(256) void cvt_all(
    const float* __restrict__ x, const float* __restrict__ wq,
    const float* __restrict__ wp)
{
    int i = blockIdx.x * 256 + threadIdx.x;
    const float* s;
    __half* d;
    if (i < N4_X)                { s = x;  d = g_xf; }
    else if (i < N4_X + N4_WQ)   { s = wq; d = g_wqf; i -= N4_X; }
    else if (i < N4_X + N4_WQ + N4_WP) { s = wp; d = g_wpf; i -= N4_X + N4_WQ; }
    else return;
    float4 v = ((const float4*)s)[i];
    ((__half2*)d)[2*i]   = __floats2half2_rn(v.x, v.y);
    ((__half2*)d)[2*i+1] = __floats2half2_rn(v.z, v.w);
}

// ---------------- fp16 GEMM, CTA 128x64, 3 CTAs/SM (high occupancy) -------
// D[m,n] = sum_k A[m,k]*W[n,k] + bias[n]
// 256 threads = 8 warps (4m x 2n), warp tile 32x32 (acc 32 regs).
// BK=32/stage (2 K16 sub-slabs), 4-stage cp.async ring, wait-depth 2.
// cp.async: 768 16B chunks/stage = exactly 3 per thread.
// MODE 0: q,k,v -> fp16 scatter [B,H,T,d].  MODE 1: fp32 row-major out.
template <int MODE>
__global__ __launch_bounds__(256, 3) void gemm_f16_kernel(
    const __half* __restrict__ Af, const __half* __restrict__ Bf,
    const float* __restrict__ bias, float* __restrict__ Cout)
{
    extern __shared__ char smem[];
    const uint32_t sb = smem_u32(smem);
    const int tid = threadIdx.x;
    const int wid = tid >> 5;
    const int lane = tid & 31;
    const int warp_m = wid & 3;      // 4 x 32 rows = 128
    const int warp_n = wid >> 2;     // 2 x 32 cols = 64
    const int bn = blockIdx.x, bm = blockIdx.y;

    // cp.async chunk map: c = tid + i*256, i=0..2 (768 chunks/stage).
    // c < 512: A (sub=(c>>8)&1, row=(c&255)>>1, half=c&1)
    // else:    B (cc=c-512, sub=(cc>>7)&1, row=(cc&127)>>1, half=cc&1)
    uint32_t cdst[3];
    const __half* csrc3[3];
    #pragma unroll
    for (int i = 0; i < 3; i++) {
        const int c = tid + i * 256;
        if (c < 512) {
            const int sub = (c >> 8) & 1, rr = c & 255;
            const int row = rr >> 1, half = rr & 1;
            cdst[i] = (uint32_t)(sub * TA16 + row * SP * 2 + half * 16);
            csrc3[i] = Af + (size_t)(bm * 128 + row) * K_ + sub * 16 + half * 8;
        } else {
            const int cc = c - 512;
            const int sub = (cc >> 7) & 1, rr = cc & 127;
            const int row = rr >> 1, half = rr & 1;
            cdst[i] = (uint32_t)(2 * TA16 + sub * TB16 + row * SP * 2 + half * 16);
            csrc3[i] = Bf + (size_t)(bn * 64 + row) * K_ + sub * 16 + half * 8;
        }
    }

    // ldmatrix per-lane byte offsets within a K16 tile
    const uint32_t aoff = (uint32_t)(
        (warp_m * 32 + (lane & 7) + ((lane >> 3) & 1) * 8) * SP
        + (lane >> 4) * 8) * 2;
    const uint32_t boff = (uint32_t)(2 * TA16) + (uint32_t)(
        (warp_n * 32 + (lane & 7) + (lane >> 4) * 8) * SP
        + ((lane >> 3) & 1) * 8) * 2;

    float acc[2][4][4];
    #pragma unroll
    for (int i = 0; i < 2; i++)
        #pragma unroll
        for (int j = 0; j < 4; j++)
            #pragma unroll
            for (int c = 0; c < 4; c++) acc[i][j][c] = 0.f;

    const int NT = K_ / 32;   // 32 iterations

    #pragma unroll
    for (int st = 0; st < NSTAGE - 1; st++) {
        #pragma unroll
        for (int i = 0; i < 3; i++)
            CP16(sb + st * STAGE_B + cdst[i], csrc3[i] + st * 32);
        CP_COMMIT();
    }

    for (int it = 0; it < NT; ++it) {
        CP_WAIT(NSTAGE - 2);
        __syncthreads();
        const uint32_t tb = sb + (uint32_t)(it & (NSTAGE - 1)) * STAGE_B;

        if (it + NSTAGE - 1 < NT) {
            const uint32_t db = sb + (uint32_t)((it + NSTAGE - 1) & (NSTAGE - 1)) * STAGE_B;
            #pragma unroll
            for (int i = 0; i < 3; i++)
                CP16(db + cdst[i], csrc3[i] + (it + NSTAGE - 1) * 32);
        }
        CP_COMMIT();

        #pragma unroll
        for (int sub = 0; sub < 2; sub++) {
            const uint32_t ta  = tb + sub * TA16;
            const uint32_t tbb = tb + sub * TB16;   // boff already has 2*TA16
            uint32_t af[2][4];
            #pragma unroll
            for (int mf = 0; mf < 2; mf++) {
                const uint32_t ao = ta + aoff + (uint32_t)(mf * 16 * SP) * 2;
                LDMX4(af[mf][0], af[mf][1], af[mf][2], af[mf][3], ao);
            }
            #pragma unroll
            for (int nf2 = 0; nf2 < 2; nf2++) {
                uint32_t bf[4];
                const uint32_t bo = tbb + boff + (uint32_t)(nf2 * 16 * SP) * 2;
                LDMX4(bf[0], bf[1], bf[2], bf[3], bo);
                #pragma unroll
                for (int mf = 0; mf < 2; mf++) {
                    MMAH16816(acc[mf][nf2*2],   af[mf][0], af[mf][1], af[mf][2], af[mf][3],
                              bf[0], bf[1]);
                    MMAH16816(acc[mf][nf2*2+1], af[mf][0], af[mf][1], af[mf][2], af[mf][3],
                              bf[2], bf[3]);
                }
            }
        }
    }
    CP_WAIT(0);

    // ---- direct-from-fragment epilogue ----
    const int g = lane >> 2, tg = lane & 3;
    #pragma unroll
    for (int mf = 0; mf < 2; mf++) {
        #pragma unroll
        for (int nf = 0; nf < 4; nf++) {
            const int gc = bn * 64 + warp_n * 32 + nf * 8 + tg * 2;
            const float b0 = bias[gc], b1 = bias[gc + 1];
            const int r0 = bm * 128 + warp_m * 32 + mf * 16 + g;
            const float v0 = acc[mf][nf][0] + b0, v1 = acc[mf][nf][1] + b1;
            const float v2 = acc[mf][nf][2] + b0, v3 = acc[mf][nf][3] + b1;
            if (MODE == 0) {
                const int sel = gc >> 10;
                const int within = gc & 1023;
                const int h = within >> 6;
                const int dd = within & 63;
                __half* dst = (sel == 0) ? g_Qf : ((sel == 1) ? g_Kf : g_Vf);
                #pragma unroll
                for (int rr = 0; rr < 2; rr++) {
                    const int m = r0 + rr * 8;
                    const int b = m >> 11, t = m & 2047;
                    const size_t o = (((size_t)(b * H_ + h)) * T_ + t) * D_ + dd;
                    *(__half2*)(dst + o) = __floats2half2_rn(rr ? v2 : v0,
                                                             rr ? v3 : v1);
                }
            } else {
                #pragma unroll
                for (int rr = 0; rr < 2; rr++) {
                    const int m = r0 + rr * 8;
                    float2 y;
                    y.x = rr ? v2 : v0;
                    y.y = rr ? v3 : v1;
                    *(float2*)(Cout + (size_t)m * C_ + gc) = y;
                }
            }
        }
    }
}

// ---------------------------------------------------------------------------
// Polynomial softcap+exp, ONE MUFU per element.
// ---------------------------------------------------------------------------
__device__ __forceinline__ float softp(float raw, bool valid) {
    const float r = fminf(fmaxf(raw, -60.0f), 60.0f);
    const float w = r * r;
    const float u = r * fmaf(fmaf(7.2473e-12f, w, -1.0436162e-6f), w,
                             0.18033688011f);
    float p;
    asm("ex2.approx.f32 %0, %1;" : "=f"(p) : "f"(u));
    return valid ? p : 0.0f;
}

__device__ __forceinline__ bool tile_valid(int kt, int q0, int P) {
    const int k0 = kt * 64;
    return (k0 < P) || ((k0 <= q0 + 127) && (k0 + 63 >= q0 - WIN_));
}

// ---------------------------------------------------------------------------
// Attention (identical to r15): 128 q-rows/CTA, 8 warps, fp16 MMA,
// cp.async double-buffered K/V with valid-tile skip list.
// ---------------------------------------------------------------------------
__global__ __launch_bounds__(256, 2) void attn_kernel(const int* __restrict__ spl)
{
    extern __shared__ __half asm_[];
    __half* Qf  = asm_;
    __half* KV0 = Qf + 128 * ASP;

    const int tid = threadIdx.x;
    const int wid = tid >> 5;
    const int lane = tid & 31;
    const int q0 = blockIdx.x * 128;
    const int h = blockIdx.y;
    const int b = blockIdx.z;
    const size_t bh = (size_t)(b * H_ + h) * T_;
    const int P = spl[b];

    for (int i = tid; i < 1024; i += 256) {
        const int r = i >> 3;
        const int c8 = i & 7;
        *(uint4*)(Qf + r * ASP + c8 * 8) =
            *(const uint4*)(g_Qf + (bh + q0 + r) * D_ + c8 * 8);
    }

    const uint32_t kv_sb = smem_u32(KV0);
    const int a_row = wid * 16 + (lane & 7) + ((lane >> 3) & 1) * 8;
    const int a_kg = (lane >> 4) * 8;
    const uint32_t qf_a = smem_u32(Qf + a_row * ASP + a_kg);
    const int k_row = (lane & 7) + (lane >> 4) * 8;
    const int k_col = ((lane >> 3) & 1) * 8;
    const uint32_t kf_a0 = kv_sb + (uint32_t)(k_row * ASP + k_col) * 2;
    const int v_row = ((lane >> 3) & 1) * 8 + (lane & 7);
    const int v_col = (lane >> 4) * 8;
    const uint32_t vf_a0 = kv_sb + (uint32_t)(64 * ASP + v_row * ASP + v_col) * 2;

    float o[8][4];
    #pragma unroll
    for (int i = 0; i < 8; i++)
        #pragma unroll
        for (int j = 0; j < 4; j++) o[i][j] = 0.f;
    float lsum0 = 0.f, lsum1 = 0.f;
    const int row0 = q0 + wid * 16 + (lane >> 2);

    auto issue_load = [&](int kt, int bsel) {
        #pragma unroll
        for (int j = 0; j < 4; j++) {
            const int c = tid + j * 256;
            const int arr = c >> 9;
            const int r = (c >> 3) & 63;
            const int c8 = c & 7;
            const __half* src = (arr ? g_Vf : g_Kf) + (bh + kt * 64 + r) * D_ + c8 * 8;
            const uint32_t dst = kv_sb + (uint32_t)(bsel * KV_BUF_H) * 2
                               + (uint32_t)(arr * 64 * ASP + r * ASP + c8 * 8) * 2;
            CP16(dst, src);
        }
    };

    int kt = 0;
    while (kt < T_ / 64 && !tile_valid(kt, q0, P)) kt++;
    if (kt < T_ / 64) issue_load(kt, 0);
    CP_COMMIT();

    int buf = 0;
    __syncthreads();

    while (kt < T_ / 64) {
        int nkt = kt + 1;
        while (nkt < T_ / 64 && !tile_valid(nkt, q0, P)) nkt++;

        CP_WAIT(0);
        __syncthreads();
        if (nkt < T_ / 64) issue_load(nkt, buf ^ 1);
        CP_COMMIT();

        const uint32_t kf_a = kf_a0 + (uint32_t)(buf * KV_BUF_H) * 2;
        const uint32_t vf_a = vf_a0 + (uint32_t)(buf * KV_BUF_H) * 2;
        const int k0 = kt * 64;

        float s[8][4];
        #pragma unroll
        for (int i = 0; i < 8; i++)
            #pragma unroll
            for (int j = 0; j < 4; j++) s[i][j] = 0.f;

        #pragma unroll
        for (int kk4 = 0; kk4 < 4; kk4++) {
            uint32_t qa[4];
            LDMX4(qa[0], qa[1], qa[2], qa[3], qf_a + kk4 * 32);
            #pragma unroll
            for (int nf2 = 0; nf2 < 4; nf2++) {
                uint32_t kb[4];
                LDMX4(kb[0], kb[1], kb[2], kb[3],
                      kf_a + (uint32_t)(nf2 * 16 * ASP) * 2 + kk4 * 32);
                MMAH16816(s[nf2*2],   qa[0], qa[1], qa[2], qa[3], kb[0], kb[1]);
                MMAH16816(s[nf2*2+1], qa[0], qa[1], qa[2], qa[3], kb[2], kb[3]);
            }
        }

        #pragma unroll
        for (int kc = 0; kc < 4; kc++) {
            uint32_t pa[4];
            #pragma unroll
            for (int j = 0; j < 2; j++) {
                const int nf = kc * 2 + j;
                const int cb = k0 + nf * 8 + (lane & 3) * 2;
                const bool va0 = ((cb     <= row0)     && (row0     - cb     <= WIN_)) || (cb     < P);
                const bool va1 = ((cb + 1 <= row0)     && (row0     - cb - 1 <= WIN_)) || (cb + 1 < P);
                const bool va2 = ((cb     <= row0 + 8) && (row0 + 8 - cb     <= WIN_)) || (cb     < P);
                const bool va3 = ((cb + 1 <= row0 + 8) && (row0 + 8 - cb - 1 <= WIN_)) || (cb + 1 < P);
                const float p0 = softp(s[nf][0], va0);
                const float p1 = softp(s[nf][1], va1);
                const float p2 = softp(s[nf][2], va2);
                const float p3 = softp(s[nf][3], va3);
                lsum0 += p0 + p1;
                lsum1 += p2 + p3;
                pa[j*2]   = packh2(p0, p1);
                pa[j*2+1] = packh2(p2, p3);
            }
            #pragma unroll
            for (int nf2 = 0; nf2 < 4; nf2++) {
                uint32_t vb[4];
                const uint32_t off = (uint32_t)(kc * 16 * ASP + nf2 * 16) * 2;
                LDMX4T(vb[0], vb[1], vb[2], vb[3], vf_a + off);
                MMAH16816(o[nf2*2],   pa[0], pa[1], pa[2], pa[3], vb[0], vb[1]);
                MMAH16816(o[nf2*2+1], pa[0], pa[1], pa[2], pa[3], vb[2], vb[3]);
            }
        }

        buf ^= 1;
        kt = nkt;
    }

    lsum0 += __shfl_xor_sync(0xffffffffu, lsum0, 1);
    lsum0 += __shfl_xor_sync(0xffffffffu, lsum0, 2);
    lsum1 += __shfl_xor_sync(0xffffffffu, lsum1, 1);
    lsum1 += __shfl_xor_sync(0xffffffffu, lsum1, 2);
    const float inv0 = 1.0f / lsum0;
    const float inv1 = 1.0f / lsum1;

    __half* yp0 = g_yf + ((size_t)(b * T_) + row0) * C_ + h * D_ + (lane & 3) * 2;
    __half* yp1 = yp0 + (size_t)8 * C_;
    #pragma unroll
    for (int nf = 0; nf < 8; nf++) {
        *(__half2*)(yp0 + nf * 8) = __floats2half2_rn(o[nf][0] * inv0,
                                                      o[nf][1] * inv0);
        *(__half2*)(yp1 + nf * 8) = __floats2half2_rn(o[nf][2] * inv1,
                                                      o[nf][3] * inv1);
    }
}

// ---------------------------------------------------------------------------
extern "C" void kernel_launch(void* const* d_in, const int* in_sizes, int n_in,
                              void* d_out, int out_size)
{
    (void)in_sizes; (void)n_in; (void)out_size;
    const float* x    = (const float*)d_in[0];
    const int*   spl  = (const int*)  d_in[1];
    const float* Wqkv = (const float*)d_in[2];
    const float* bqkv = (const float*)d_in[3];
    const float* Wprj = (const float*)d_in[4];
    const float* bprj = (const float*)d_in[5];
    float* out = (float*)d_out;

    cudaFuncSetAttribute(gemm_f16_kernel<0>,
                         cudaFuncAttributeMaxDynamicSharedMemorySize, GSMEM);
    cudaFuncSetAttribute(gemm_f16_kernel<1>,
                         cudaFuncAttributeMaxDynamicSharedMemorySize, GSMEM);
    cudaFuncSetAttribute(attn_kernel,
                         cudaFuncAttributeMaxDynamicSharedMemorySize, ATTN_SMEM);

    __half *xf, *wqf, *wpf, *yf;
    cudaGetSymbolAddress((void**)&xf,  g_xf);
    cudaGetSymbolAddress((void**)&wqf, g_wqf);
    cudaGetSymbolAddress((void**)&wpf, g_wpf);
    cudaGetSymbolAddress((void**)&yf,  g_yf);

    // 0) fused fp32->fp16 conversion (single launch)
    const int n4_total = N4_X + N4_WQ + N4_WP;
    cvt_all<<<(n4_total + 255) / 256, 256>>>(x, Wqkv, Wprj);

    // 1) QKV projection (fp16 HMMA, 128x64 tiles, 3 CTAs/SM)
    gemm_f16_kernel<0><<<dim3(3*C_/64, B_*T_/128), 256, GSMEM>>>(
        xf, wqf, bqkv, nullptr);

    // 2) attention (fp16 MMA, cp.async double-buffered K/V) -> g_yf
    attn_kernel<<<dim3(T_/128, H_, B_), 256, ATTN_SMEM>>>(spl);

    // 3) output projection (fp16 HMMA, 128x64 tiles, 3 CTAs/SM) -> d_out
    gemm_f16_kernel<1><<<dim3(C_/64, B_*T_/128), 256, GSMEM>>>(
        yf, wpf, bprj, out);
}

// round 17
// speedup vs baseline: 1.1212x; 1.1212x over previous
#include <cuda_runtime.h>
#include <cuda_bf16.h>
#include <cuda_fp16.h>
#include <math.h>
#include <stdint.h>

// Problem constants
#define B_ 2
#define T_ 2048
#define C_ 1024
#define H_ 16
#define D_ 64
#define WIN_ 512
#define K_ 1024

// GEMM tiling: CTA 128x128, 256 thr, warp 64x32, BK=32/stage, 4 stages, 2 CTA/SM
#define SP 24                         // padded row stride per K16 tile (fp16) = 48 B
#define TA16 (128 * SP * 2)           // 6144 B per 128x16 tile (A and B same)
#define TB16 (128 * SP * 2)
#define STAGE_B (2 * (TA16 + TB16))   // 24576 B (2 K16 sub-slabs)
#define NSTAGE 4                      // power of 2 (ring mask)
#define GSMEM (NSTAGE * STAGE_B)      // 98304 B; 2 CTAs/SM = 192 KB

// Attention smem: Qf[128*ASP] + 2 KV buffers of (K 64*ASP + V 64*ASP)
#define ASP 72
#define KV_BUF_H (128 * ASP)                 // halves per KV buffer (K+V)
#define ATTN_SMEM ((128 * ASP + 2 * KV_BUF_H) * 2)   // 55296 B

// ---------------- scratch (allocation-free) ----------------
__device__ __half g_Qf[B_*H_*T_*D_];
__device__ __half g_Kf[B_*H_*T_*D_];
__device__ __half g_Vf[B_*H_*T_*D_];
__device__ __half g_xf[B_*T_*C_];
__device__ __half g_wqf[3*C_*C_];
__device__ __half g_wpf[C_*C_];
__device__ __half g_yf[B_*T_*C_];

__device__ __forceinline__ uint32_t smem_u32(const void* p) {
    uint32_t a;
    asm("{ .reg .u64 t; cvta.to.shared.u64 t, %1; cvt.u32.u64 %0, t; }"
        : "=r"(a) : "l"(p));
    return a;
}
#define LDMX4(r0, r1, r2, r3, addr)                                          \
    asm volatile("ldmatrix.sync.aligned.m8n8.x4.shared.b16 {%0,%1,%2,%3}, [%4];" \
        : "=r"(r0), "=r"(r1), "=r"(r2), "=r"(r3) : "r"(addr))
#define LDMX4T(r0, r1, r2, r3, addr)                                         \
    asm volatile("ldmatrix.sync.aligned.m8n8.x4.trans.shared.b16 {%0,%1,%2,%3}, [%4];" \
        : "=r"(r0), "=r"(r1), "=r"(r2), "=r"(r3) : "r"(addr))
// fp16 HMMA
#define MMAH16816(c, a0, a1, a2, a3, b0, b1)                                 \
    asm volatile("mma.sync.aligned.m16n8k16.row.col.f32.f16.f16.f32 "        \
        "{%0,%1,%2,%3}, {%4,%5,%6,%7}, {%8,%9}, {%0,%1,%2,%3};"              \
        : "+f"((c)[0]), "+f"((c)[1]), "+f"((c)[2]), "+f"((c)[3])             \
        : "r"(a0), "r"(a1), "r"(a2), "r"(a3), "r"(b0), "r"(b1))
#define CP16(dst, src)                                                       \
    asm volatile("cp.async.cg.shared.global [%0], [%1], 16;" :: "r"(dst), "l"(src))
#define CP_COMMIT() asm volatile("cp.async.commit_group;" ::: "memory")
#define CP_WAIT(n)  asm volatile("cp.async.wait_group %0;" :: "n"(n) : "memory")

__device__ __forceinline__ uint32_t packh2(float a, float b) {
    __half2 h = __floats2half2_rn(a, b);
    return *(uint32_t*)&h;
}

// ---------------- fused fp32->fp16 convert for x, Wqkv, Wproj -------------
#define N4_X  (B_*T_*C_/4)
#define N4_WQ (3*C_*C_/4)
#define N4_WP (C_*C_/4)
__global__ __launch_bounds__(256) void cvt_all(
    const float* __restrict__ x, const float* __restrict__ wq,
    const float* __restrict__ wp)
{
    int i = blockIdx.x * 256 + threadIdx.x;
    const float* s;
    __half* d;
    if (i < N4_X)                { s = x;  d = g_xf; }
    else if (i < N4_X + N4_WQ)   { s = wq; d = g_wqf; i -= N4_X; }
    else if (i < N4_X + N4_WQ + N4_WP) { s = wp; d = g_wpf; i -= N4_X + N4_WQ; }
    else return;
    float4 v = ((const float4*)s)[i];
    ((__half2*)d)[2*i]   = __floats2half2_rn(v.x, v.y);
    ((__half2*)d)[2*i+1] = __floats2half2_rn(v.z, v.w);
}

// ---------------- fp16 GEMM, CTA 128x128, 2 CTAs/SM ------------------------
// D[m,n] = sum_k A[m,k]*W[n,k] + bias[n]
// 256 threads = 8 warps (2m x 4n), warp tile 64x32 (r14's per-warp structure:
// 6 LDSM : 16 MMA per K16 sub-slab). BK=32/stage, 4-stage ring, wait-depth 2.
// 2 CTAs/SM so the other CTA's warps cover barrier/wait drain.
// cp.async: 1024 16B chunks/stage = exactly 4 per thread.
// MODE 0: q,k,v -> fp16 scatter [B,H,T,d].  MODE 1: fp32 row-major out.
template <int MODE>
__global__ __launch_bounds__(256, 2) void gemm_f16_kernel(
    const __half* __restrict__ Af, const __half* __restrict__ Bf,
    const float* __restrict__ bias, float* __restrict__ Cout)
{
    extern __shared__ char smem[];
    const uint32_t sb = smem_u32(smem);
    const int tid = threadIdx.x;
    const int wid = tid >> 5;
    const int lane = tid & 31;
    const int warp_m = wid & 1;      // 2 x 64 rows = 128
    const int warp_n = wid >> 1;     // 4 x 32 cols = 128
    const int bn = blockIdx.x, bm = blockIdx.y;

    // cp.async chunk map: c = tid + i*256, i=0..3 (1024 chunks/stage).
    // c < 512: A (row=c>>2, j=c&3); else B (cc=c-512 likewise).
    // j: sub-slab = j>>1, 16B half = j&1.
    uint32_t cdst[4];
    const __half* csrc4[4];
    #pragma unroll
    for (int i = 0; i < 4; i++) {
        const int c = tid + i * 256;
        const bool isA = c < 512;
        const int cc = isA ? c : c - 512;
        const int row = cc >> 2, j = cc & 3;
        const int sub = j >> 1, half = j & 1;
        cdst[i] = (isA ? (uint32_t)(sub * TA16)
                       : (uint32_t)(2 * TA16 + sub * TB16))
                  + (uint32_t)(row * SP * 2 + half * 16);
        csrc4[i] = (isA ? Af + (size_t)(bm * 128 + row) * K_
                        : Bf + (size_t)(bn * 128 + row) * K_)
                   + sub * 16 + half * 8;
    }

    // ldmatrix per-lane byte offsets within a K16 tile
    const uint32_t aoff = (uint32_t)(
        (warp_m * 64 + (lane & 7) + ((lane >> 3) & 1) * 8) * SP
        + (lane >> 4) * 8) * 2;
    const uint32_t boff = (uint32_t)(2 * TA16) + (uint32_t)(
        (warp_n * 32 + (lane & 7) + (lane >> 4) * 8) * SP
        + ((lane >> 3) & 1) * 8) * 2;

    float acc[4][4][4];
    #pragma unroll
    for (int i = 0; i < 4; i++)
        #pragma unroll
        for (int j = 0; j < 4; j++)
            #pragma unroll
            for (int c = 0; c < 4; c++) acc[i][j][c] = 0.f;

    const int NT = K_ / 32;   // 32 iterations

    #pragma unroll
    for (int st = 0; st < NSTAGE - 1; st++) {
        #pragma unroll
        for (int i = 0; i < 4; i++)
            CP16(sb + st * STAGE_B + cdst[i], csrc4[i] + st * 32);
        CP_COMMIT();
    }

    for (int it = 0; it < NT; ++it) {
        CP_WAIT(NSTAGE - 2);
        __syncthreads();
        const uint32_t tb = sb + (uint32_t)(it & (NSTAGE - 1)) * STAGE_B;

        if (it + NSTAGE - 1 < NT) {
            const uint32_t db = sb + (uint32_t)((it + NSTAGE - 1) & (NSTAGE - 1)) * STAGE_B;
            #pragma unroll
            for (int i = 0; i < 4; i++)
                CP16(db + cdst[i], csrc4[i] + (it + NSTAGE - 1) * 32);
        }
        CP_COMMIT();

        #pragma unroll
        for (int sub = 0; sub < 2; sub++) {
            const uint32_t ta  = tb + sub * TA16;
            const uint32_t tbb = tb + sub * TB16;   // boff already has 2*TA16
            uint32_t af[4][4];
            #pragma unroll
            for (int mf = 0; mf < 4; mf++) {
                const uint32_t ao = ta + aoff + (uint32_t)(mf * 16 * SP) * 2;
                LDMX4(af[mf][0], af[mf][1], af[mf][2], af[mf][3], ao);
            }
            #pragma unroll
            for (int nf2 = 0; nf2 < 2; nf2++) {
                uint32_t bf[4];
                const uint32_t bo = tbb + boff + (uint32_t)(nf2 * 16 * SP) * 2;
                LDMX4(bf[0], bf[1], bf[2], bf[3], bo);
                #pragma unroll
                for (int mf = 0; mf < 4; mf++) {
                    MMAH16816(acc[mf][nf2*2],   af[mf][0], af[mf][1], af[mf][2], af[mf][3],
                              bf[0], bf[1]);
                    MMAH16816(acc[mf][nf2*2+1], af[mf][0], af[mf][1], af[mf][2], af[mf][3],
                              bf[2], bf[3]);
                }
            }
        }
    }
    CP_WAIT(0);

    // ---- direct-from-fragment epilogue ----
    const int g = lane >> 2, tg = lane & 3;
    #pragma unroll
    for (int mf = 0; mf < 4; mf++) {
        #pragma unroll
        for (int nf = 0; nf < 4; nf++) {
            const int gc = bn * 128 + warp_n * 32 + nf * 8 + tg * 2;
            const float b0 = bias[gc], b1 = bias[gc + 1];
            const int r0 = bm * 128 + warp_m * 64 + mf * 16 + g;
            const float v0 = acc[mf][nf][0] + b0, v1 = acc[mf][nf][1] + b1;
            const float v2 = acc[mf][nf][2] + b0, v3 = acc[mf][nf][3] + b1;
            if (MODE == 0) {
                const int sel = gc >> 10;
                const int within = gc & 1023;
                const int h = within >> 6;
                const int dd = within & 63;
                __half* dst = (sel == 0) ? g_Qf : ((sel == 1) ? g_Kf : g_Vf);
                #pragma unroll
                for (int rr = 0; rr < 2; rr++) {
                    const int m = r0 + rr * 8;
                    const int b = m >> 11, t = m & 2047;
                    const size_t o = (((size_t)(b * H_ + h)) * T_ + t) * D_ + dd;
                    *(__half2*)(dst + o) = __floats2half2_rn(rr ? v2 : v0,
                                                             rr ? v3 : v1);
                }
            } else {
                #pragma unroll
                for (int rr = 0; rr < 2; rr++) {
                    const int m = r0 + rr * 8;
                    float2 y;
                    y.x = rr ? v2 : v0;
                    y.y = rr ? v3 : v1;
                    *(float2*)(Cout + (size_t)m * C_ + gc) = y;
                }
            }
        }
    }
}

// ---------------------------------------------------------------------------
// Polynomial softcap+exp, ONE MUFU per element.
// ---------------------------------------------------------------------------
__device__ __forceinline__ float softp(float raw, bool valid) {
    const float r = fminf(fmaxf(raw, -60.0f), 60.0f);
    const float w = r * r;
    const float u = r * fmaf(fmaf(7.2473e-12f, w, -1.0436162e-6f), w,
                             0.18033688011f);
    float p;
    asm("ex2.approx.f32 %0, %1;" : "=f"(p) : "f"(u));
    return valid ? p : 0.0f;
}

__device__ __forceinline__ bool tile_valid(int kt, int q0, int P) {
    const int k0 = kt * 64;
    return (k0 < P) || ((k0 <= q0 + 127) && (k0 + 63 >= q0 - WIN_));
}

// ---------------------------------------------------------------------------
// Attention (identical to r15): 128 q-rows/CTA, 8 warps, fp16 MMA,
// cp.async double-buffered K/V with valid-tile skip list.
// ---------------------------------------------------------------------------
__global__ __launch_bounds__(256, 2) void attn_kernel(const int* __restrict__ spl)
{
    extern __shared__ __half asm_[];
    __half* Qf  = asm_;
    __half* KV0 = Qf + 128 * ASP;

    const int tid = threadIdx.x;
    const int wid = tid >> 5;
    const int lane = tid & 31;
    const int q0 = blockIdx.x * 128;
    const int h = blockIdx.y;
    const int b = blockIdx.z;
    const size_t bh = (size_t)(b * H_ + h) * T_;
    const int P = spl[b];

    for (int i = tid; i < 1024; i += 256) {
        const int r = i >> 3;
        const int c8 = i & 7;
        *(uint4*)(Qf + r * ASP + c8 * 8) =
            *(const uint4*)(g_Qf + (bh + q0 + r) * D_ + c8 * 8);
    }

    const uint32_t kv_sb = smem_u32(KV0);
    const int a_row = wid * 16 + (lane & 7) + ((lane >> 3) & 1) * 8;
    const int a_kg = (lane >> 4) * 8;
    const uint32_t qf_a = smem_u32(Qf + a_row * ASP + a_kg);
    const int k_row = (lane & 7) + (lane >> 4) * 8;
    const int k_col = ((lane >> 3) & 1) * 8;
    const uint32_t kf_a0 = kv_sb + (uint32_t)(k_row * ASP + k_col) * 2;
    const int v_row = ((lane >> 3) & 1) * 8 + (lane & 7);
    const int v_col = (lane >> 4) * 8;
    const uint32_t vf_a0 = kv_sb + (uint32_t)(64 * ASP + v_row * ASP + v_col) * 2;

    float o[8][4];
    #pragma unroll
    for (int i = 0; i < 8; i++)
        #pragma unroll
        for (int j = 0; j < 4; j++) o[i][j] = 0.f;
    float lsum0 = 0.f, lsum1 = 0.f;
    const int row0 = q0 + wid * 16 + (lane >> 2);

    auto issue_load = [&](int kt, int bsel) {
        #pragma unroll
        for (int j = 0; j < 4; j++) {
            const int c = tid + j * 256;
            const int arr = c >> 9;
            const int r = (c >> 3) & 63;
            const int c8 = c & 7;
            const __half* src = (arr ? g_Vf : g_Kf) + (bh + kt * 64 + r) * D_ + c8 * 8;
            const uint32_t dst = kv_sb + (uint32_t)(bsel * KV_BUF_H) * 2
                               + (uint32_t)(arr * 64 * ASP + r * ASP + c8 * 8) * 2;
            CP16(dst, src);
        }
    };

    int kt = 0;
    while (kt < T_ / 64 && !tile_valid(kt, q0, P)) kt++;
    if (kt < T_ / 64) issue_load(kt, 0);
    CP_COMMIT();

    int buf = 0;
    __syncthreads();

    while (kt < T_ / 64) {
        int nkt = kt + 1;
        while (nkt < T_ / 64 && !tile_valid(nkt, q0, P)) nkt++;

        CP_WAIT(0);
        __syncthreads();
        if (nkt < T_ / 64) issue_load(nkt, buf ^ 1);
        CP_COMMIT();

        const uint32_t kf_a = kf_a0 + (uint32_t)(buf * KV_BUF_H) * 2;
        const uint32_t vf_a = vf_a0 + (uint32_t)(buf * KV_BUF_H) * 2;
        const int k0 = kt * 64;

        float s[8][4];
        #pragma unroll
        for (int i = 0; i < 8; i++)
            #pragma unroll
            for (int j = 0; j < 4; j++) s[i][j] = 0.f;

        #pragma unroll
        for (int kk4 = 0; kk4 < 4; kk4++) {
            uint32_t qa[4];
            LDMX4(qa[0], qa[1], qa[2], qa[3], qf_a + kk4 * 32);
            #pragma unroll
            for (int nf2 = 0; nf2 < 4; nf2++) {
                uint32_t kb[4];
                LDMX4(kb[0], kb[1], kb[2], kb[3],
                      kf_a + (uint32_t)(nf2 * 16 * ASP) * 2 + kk4 * 32);
                MMAH16816(s[nf2*2],   qa[0], qa[1], qa[2], qa[3], kb[0], kb[1]);
                MMAH16816(s[nf2*2+1], qa[0], qa[1], qa[2], qa[3], kb[2], kb[3]);
            }
        }

        #pragma unroll
        for (int kc = 0; kc < 4; kc++) {
            uint32_t pa[4];
            #pragma unroll
            for (int j = 0; j < 2; j++) {
                const int nf = kc * 2 + j;
                const int cb = k0 + nf * 8 + (lane & 3) * 2;
                const bool va0 = ((cb     <= row0)     && (row0     - cb     <= WIN_)) || (cb     < P);
                const bool va1 = ((cb + 1 <= row0)     && (row0     - cb - 1 <= WIN_)) || (cb + 1 < P);
                const bool va2 = ((cb     <= row0 + 8) && (row0 + 8 - cb     <= WIN_)) || (cb     < P);
                const bool va3 = ((cb + 1 <= row0 + 8) && (row0 + 8 - cb - 1 <= WIN_)) || (cb + 1 < P);
                const float p0 = softp(s[nf][0], va0);
                const float p1 = softp(s[nf][1], va1);
                const float p2 = softp(s[nf][2], va2);
                const float p3 = softp(s[nf][3], va3);
                lsum0 += p0 + p1;
                lsum1 += p2 + p3;
                pa[j*2]   = packh2(p0, p1);
                pa[j*2+1] = packh2(p2, p3);
            }
            #pragma unroll
            for (int nf2 = 0; nf2 < 4; nf2++) {
                uint32_t vb[4];
                const uint32_t off = (uint32_t)(kc * 16 * ASP + nf2 * 16) * 2;
                LDMX4T(vb[0], vb[1], vb[2], vb[3], vf_a + off);
                MMAH16816(o[nf2*2],   pa[0], pa[1], pa[2], pa[3], vb[0], vb[1]);
                MMAH16816(o[nf2*2+1], pa[0], pa[1], pa[2], pa[3], vb[2], vb[3]);
            }
        }

        buf ^= 1;
        kt = nkt;
    }

    lsum0 += __shfl_xor_sync(0xffffffffu, lsum0, 1);
    lsum0 += __shfl_xor_sync(0xffffffffu, lsum0, 2);
    lsum1 += __shfl_xor_sync(0xffffffffu, lsum1, 1);
    lsum1 += __shfl_xor_sync(0xffffffffu, lsum1, 2);
    const float inv0 = 1.0f / lsum0;
    const float inv1 = 1.0f / lsum1;

    __half* yp0 = g_yf + ((size_t)(b * T_) + row0) * C_ + h * D_ + (lane & 3) * 2;
    __half* yp1 = yp0 + (size_t)8 * C_;
    #pragma unroll
    for (int nf = 0; nf < 8; nf++) {
        *(__half2*)(yp0 + nf * 8) = __floats2half2_rn(o[nf][0] * inv0,
                                                      o[nf][1] * inv0);
        *(__half2*)(yp1 + nf * 8) = __floats2half2_rn(o[nf][2] * inv1,
                                                      o[nf][3] * inv1);
    }
}

// ---------------------------------------------------------------------------
extern "C" void kernel_launch(void* const* d_in, const int* in_sizes, int n_in,
                              void* d_out, int out_size)
{
    (void)in_sizes; (void)n_in; (void)out_size;
    const float* x    = (const float*)d_in[0];
    const int*   spl  = (const int*)  d_in[1];
    const float* Wqkv = (const float*)d_in[2];
    const float* bqkv = (const float*)d_in[3];
    const float* Wprj = (const float*)d_in[4];
    const float* bprj = (const float*)d_in[5];
    float* out = (float*)d_out;

    cudaFuncSetAttribute(gemm_f16_kernel<0>,
                         cudaFuncAttributeMaxDynamicSharedMemorySize, GSMEM);
    cudaFuncSetAttribute(gemm_f16_kernel<1>,
                         cudaFuncAttributeMaxDynamicSharedMemorySize, GSMEM);
    cudaFuncSetAttribute(attn_kernel,
                         cudaFuncAttributeMaxDynamicSharedMemorySize, ATTN_SMEM);

    __half *xf, *wqf, *wpf, *yf;
    cudaGetSymbolAddress((void**)&xf,  g_xf);
    cudaGetSymbolAddress((void**)&wqf, g_wqf);
    cudaGetSymbolAddress((void**)&wpf, g_wpf);
    cudaGetSymbolAddress((void**)&yf,  g_yf);

    // 0) fused fp32->fp16 conversion (single launch)
    const int n4_total = N4_X + N4_WQ + N4_WP;
    cvt_all<<<(n4_total + 255) / 256, 256>>>(x, Wqkv, Wprj);

    // 1) QKV projection (fp16 HMMA, 128x128 tiles, 2 CTAs/SM)
    gemm_f16_kernel<0><<<dim3(3*C_/128, B_*T_/128), 256, GSMEM>>>(
        xf, wqf, bqkv, nullptr);

    // 2) attention (fp16 MMA, cp.async double-buffered K/V) -> g_yf
    attn_kernel<<<dim3(T_/128, H_, B_), 256, ATTN_SMEM>>>(spl);

    // 3) output projection (fp16 HMMA, 128x128 tiles, 2 CTAs/SM) -> d_out
    gemm_f16_kernel<1><<<dim3(C_/128, B_*T_/128), 256, GSMEM>>>(
        yf, wpf, bprj, out);
}